// round 15
// baseline (speedup 1.0000x reference)
#include <cuda_runtime.h>
#include <cuda_bf16.h>
#include <math.h>

// ---------------------------------------------------------------------------
// DetBenchPredict: EfficientDet postprocess
//   B=16 images, 49104 anchors, 90 classes, top-5000, NMS(0.5) -> 100 dets
// ---------------------------------------------------------------------------

#define NIMG 16
#define NCLS 90
#define KSEL 5000
#define SLOTS 5024
#define CAP 65536
#define NDET 100
#define TCAP 1024
#define BCAP 512
#define SKEY_CAP 32768
#define GCAP 1024
#define GTARGET 950
#define NBINS 4096

// Device scratch (128B-strided counters -> separate L2 slices).
__device__ unsigned g_cnt[NIMG * 32];
__device__ unsigned g_key[(size_t)NIMG * CAP];
__device__ unsigned g_idx[(size_t)NIMG * CAP];
__device__ unsigned long long g_sel[(size_t)NIMG * SLOTS];
__device__ unsigned long long g_rank[(size_t)NIMG * SLOTS];
__device__ float4 g_box[(size_t)NIMG * SLOTS];
__device__ int g_meta[NIMG * 32];
__device__ unsigned g_maxb[NIMG * 32];
__device__ unsigned g_thrK[NIMG * 32];
__device__ unsigned g_maxk[NIMG * 32];

// -------------------------------- collect pass -----------------------------
__global__ void __launch_bounds__(256)
k_collect(const float4* __restrict__ c0, const float4* __restrict__ c1,
          const float4* __restrict__ c2, const float4* __restrict__ c3,
          const float4* __restrict__ c4) {
    __shared__ unsigned sCnt, sBase;
    __shared__ unsigned sKeyB[BCAP];
    __shared__ unsigned sIdxB[BCAP];

    const int img = blockIdx.y;
    const int b = blockIdx.x;
    const int tid = threadIdx.x;
    if (tid == 0) sCnt = 0;
    __syncthreads();

    const float4* p;
    int n4, lf, aOff, start;
    bool check;
    if (b < 405)      { p = c0; n4 = 829440; lf = 6; aOff = 0;     start = b * 2048;         check = false; }
    else if (b < 506) { p = c1; n4 = 207360; lf = 5; aOff = 36864; start = (b - 405) * 2048; check = false; }
    else if (b == 506){ p = c1; n4 = 207360; lf = 5; aOff = 36864; start = 206848;           check = true;  }
    else if (b < 532) { p = c2; n4 = 51840;  lf = 4; aOff = 46080; start = (b - 507) * 2048; check = false; }
    else if (b == 532){ p = c2; n4 = 51840;  lf = 4; aOff = 46080; start = 51200;            check = true;  }
    else if (b < 539) { p = c3; n4 = 12960;  lf = 3; aOff = 48384; start = (b - 533) * 2048; check = false; }
    else if (b == 539){ p = c3; n4 = 12960;  lf = 3; aOff = 48384; start = 12288;            check = true;  }
    else if (b == 540){ p = c4; n4 = 3240;   lf = 2; aOff = 48960; start = 0;                check = false; }
    else              { p = c4; n4 = 3240;   lf = 2; aOff = 48960; start = 2048;             check = true;  }

    p += (size_t)img * n4;
    const int i0 = start + tid;

    float4 v[8];
    if (!check) {
#pragma unroll
        for (int k = 0; k < 8; k++) v[k] = p[i0 + k * 256];
    } else {
#pragma unroll
        for (int k = 0; k < 8; k++) {
            int i = i0 + k * 256;
            v[k] = (i < n4) ? p[i] : make_float4(-9.f, -9.f, -9.f, -9.f);
        }
    }

    float mf = fmaxf(fmaxf(fmaxf(v[0].x, v[0].y), fmaxf(v[0].z, v[0].w)),
                     fmaxf(fmaxf(v[1].x, v[1].y), fmaxf(v[1].z, v[1].w)));
    mf = fmaxf(mf, fmaxf(fmaxf(fmaxf(v[2].x, v[2].y), fmaxf(v[2].z, v[2].w)),
                         fmaxf(fmaxf(v[3].x, v[3].y), fmaxf(v[3].z, v[3].w))));
    unsigned mu = min(min(min(__float_as_uint(v[4].x), __float_as_uint(v[4].y)),
                          min(__float_as_uint(v[4].z), __float_as_uint(v[4].w))),
                      min(min(__float_as_uint(v[5].x), __float_as_uint(v[5].y)),
                          min(__float_as_uint(v[5].z), __float_as_uint(v[5].w))));
    mu = min(mu,
             min(min(min(__float_as_uint(v[6].x), __float_as_uint(v[6].y)),
                     min(__float_as_uint(v[6].z), __float_as_uint(v[6].w))),
                 min(min(__float_as_uint(v[7].x), __float_as_uint(v[7].y)),
                     min(__float_as_uint(v[7].z), __float_as_uint(v[7].w)))));
    bool hit = (mf > -1.5f) || (mu < 0xBFC00000u);

    if (__ballot_sync(0xffffffffu, hit)) {
        if (hit) {
            const int f = 1 << lf;
            const int ff = 1 << (2 * lf);
#pragma unroll
            for (int k = 0; k < 8; k++) {
                int i = i0 + k * 256;
                float vs[4] = {v[k].x, v[k].y, v[k].z, v[k].w};
#pragma unroll
                for (int j = 0; j < 4; j++) {
                    if (vs[j] > -1.5f) {
                        int t = i * 4 + j;
                        int ch = t >> (2 * lf);
                        int r = t & (ff - 1);
                        int y = r >> lf;
                        int x = r & (f - 1);
                        int a = ch / NCLS;
                        int c = ch - a * NCLS;
                        unsigned flat =
                            (unsigned)((aOff + (y * f + x) * 9 + a) * NCLS + c);
                        unsigned u = __float_as_uint(vs[j]);
                        unsigned key = (u & 0x80000000u) ? ~u : (u | 0x80000000u);
                        unsigned pos = atomicAdd(&sCnt, 1u);
                        if (pos < BCAP) {
                            sKeyB[pos] = key;
                            sIdxB[pos] = flat;
                        } else {
                            unsigned g = atomicAdd(&g_cnt[img * 32], 1u);
                            if (g < CAP) {
                                g_key[(size_t)img * CAP + g] = key;
                                g_idx[(size_t)img * CAP + g] = flat;
                            }
                        }
                    }
                }
            }
        }
    }
    __syncthreads();
    unsigned n = sCnt;
    if (n > BCAP) n = BCAP;
    if (tid == 0 && n) sBase = atomicAdd(&g_cnt[img * 32], n);
    __syncthreads();
    if (n) {
        unsigned base = sBase;
        for (unsigned i = tid; i < n; i += 256) {
            unsigned pos = base + i;
            if (pos < CAP) {
                g_key[(size_t)img * CAP + pos] = sKeyB[i];
                g_idx[(size_t)img * CAP + pos] = sIdxB[i];
            }
        }
    }
}

// spread 4 bytes into 16-bit fields of a u64
__device__ __forceinline__ unsigned long long spread4(unsigned x) {
    unsigned long long t = x;
    t = (t | (t << 16)) & 0x0000FFFF0000FFFFull;
    t = (t | (t << 8)) & 0x00FF00FF00FF00FFull;
    return t;
}

// -------------------------------- k_sel ------------------------------------
extern "C" __global__ void __launch_bounds__(1024, 1) k_sel() {
    extern __shared__ unsigned sKeys[];
    __shared__ unsigned tieIdx[TCAP];
    __shared__ unsigned long long sWS[64];
    __shared__ unsigned redM[32];
    __shared__ unsigned tieCnt;
    __shared__ int selCnt;
    __shared__ int sChosen, sAbove;

    const int img = blockIdx.x;
    const int tid = threadIdx.x;
    const int lane = tid & 31;
    const int wid = tid >> 5;
    const unsigned lt = (1u << lane) - 1u;

    unsigned C = g_cnt[img * 32];
    if (C > CAP) C = CAP;
    const unsigned* keys = &g_key[(size_t)img * CAP];
    const unsigned* idxs = &g_idx[(size_t)img * CAP];
    if (tid == 0) { tieCnt = 0; selCnt = 0; }

    const unsigned S = C < SKEY_CAP ? C : SKEY_CAP;
    unsigned mk = 0;
    for (unsigned c = tid; c < S; c += 1024) {
        unsigned k = keys[c];
        sKeys[c] = k;
        mk = max(mk, k);
    }
    for (unsigned c = S + tid; c < C; c += 1024) mk = max(mk, keys[c]);
    const int S4 = (int)((S + 3) >> 2);
    for (unsigned c = S + tid; c < (unsigned)(S4 * 4); c += 1024) sKeys[c] = 0;
#pragma unroll
    for (int o = 16; o; o >>= 1)
        mk = max(mk, __shfl_down_sync(0xffffffffu, mk, o));
    if (lane == 0) redM[wid] = mk;
    __syncthreads();
    if (tid == 0) {
        unsigned m = 0;
        for (int w = 0; w < 32; w++) m = max(m, redM[w]);
        g_maxk[img * 32] = m;
    }

    unsigned K = 0;
    int needEq = 0;
    const bool selectAll = (C <= KSEL);
    if (!selectAll) {
        unsigned pm = 0, pv = 0;
        int k = KSEL;
        const uint4* k4 = (const uint4*)sKeys;
        for (int sh = 30; sh >= 0; sh -= 3) {
            unsigned long long c64 = 0;
            for (int i = tid; i < S4; i += 1024) {
                uint4 kk = k4[i];
                if ((kk.x & pm) == pv) c64 += 1ull << (((kk.x >> sh) & 7u) * 8);
                if ((kk.y & pm) == pv) c64 += 1ull << (((kk.y >> sh) & 7u) * 8);
                if ((kk.z & pm) == pv) c64 += 1ull << (((kk.z >> sh) & 7u) * 8);
                if ((kk.w & pm) == pv) c64 += 1ull << (((kk.w >> sh) & 7u) * 8);
            }
            for (unsigned c = S + tid; c < C; c += 1024) {
                unsigned kk = keys[c];
                if ((kk & pm) == pv) c64 += 1ull << (((kk >> sh) & 7u) * 8);
            }
            unsigned long long lo = spread4((unsigned)c64);
            unsigned long long hi = spread4((unsigned)(c64 >> 32));
#pragma unroll
            for (int o = 16; o; o >>= 1) {
                lo += __shfl_down_sync(0xffffffffu, lo, o);
                hi += __shfl_down_sync(0xffffffffu, hi, o);
            }
            if (lane == 0) { sWS[wid * 2] = lo; sWS[wid * 2 + 1] = hi; }
            __syncthreads();
            if (wid == 0) {
                lo = sWS[lane * 2];
                hi = sWS[lane * 2 + 1];
#pragma unroll
                for (int o = 16; o; o >>= 1) {
                    lo += __shfl_down_sync(0xffffffffu, lo, o);
                    hi += __shfl_down_sync(0xffffffffu, hi, o);
                }
                if (lane == 0) {
                    unsigned cnt[8];
                    cnt[0] = (unsigned)(lo & 0xFFFF);
                    cnt[1] = (unsigned)((lo >> 16) & 0xFFFF);
                    cnt[2] = (unsigned)((lo >> 32) & 0xFFFF);
                    cnt[3] = (unsigned)((lo >> 48) & 0xFFFF);
                    cnt[4] = (unsigned)(hi & 0xFFFF);
                    cnt[5] = (unsigned)((hi >> 16) & 0xFFFF);
                    cnt[6] = (unsigned)((hi >> 32) & 0xFFFF);
                    cnt[7] = (unsigned)((hi >> 48) & 0xFFFF);
                    unsigned cum = 0;
                    int ch = 0;
                    unsigned ab = 0;
                    for (int b = 7; b >= 0; b--) {
                        if (cum + cnt[b] >= (unsigned)k) { ch = b; ab = cum; break; }
                        cum += cnt[b];
                    }
                    sChosen = ch;
                    sAbove = (int)ab;
                }
            }
            __syncthreads();
            pv |= ((unsigned)sChosen) << sh;
            pm |= 7u << sh;
            k -= sAbove;
        }
        K = pv;
        needEq = k;
    }
    __syncthreads();

    unsigned long long* sel = &g_sel[(size_t)img * SLOTS];
    const unsigned Cr = ((C + 1023u) / 1024u) * 1024u;
    for (unsigned c = tid; c < Cr; c += 1024) {
        bool inb = c < C;
        unsigned key = inb ? (c < S ? sKeys[c] : keys[c]) : 0u;
        bool take = inb && (selectAll || key > K);
        bool tie = inb && !selectAll && (key == K);
        unsigned m = __ballot_sync(0xffffffffu, take);
        if (m) {
            int leader = __ffs(m) - 1;
            unsigned base = 0;
            if (lane == leader) base = (unsigned)atomicAdd(&selCnt, __popc(m));
            base = __shfl_sync(0xffffffffu, base, leader);
            if (take) {
                unsigned pos = base + (unsigned)__popc(m & lt);
                if (pos < SLOTS)
                    sel[pos] = ((unsigned long long)key << 32) | c;
            }
        }
        if (tie) {
            unsigned tp = atomicAdd(&tieCnt, 1u);
            if (tp < TCAP) tieIdx[tp] = c;
        }
    }
    __syncthreads();

    if (!selectAll) {
        int mt = tieCnt < TCAP ? (int)tieCnt : TCAP;
        for (int t = tid; t < mt; t += 1024) {
            unsigned c = tieIdx[t];
            unsigned my = idxs[c];
            int r = 0;
            for (int j = 0; j < mt; j++) r += (idxs[tieIdx[j]] < my) ? 1 : 0;
            if (r < needEq) {
                int pos = atomicAdd(&selCnt, 1);
                if (pos < SLOTS)
                    sel[pos] = ((unsigned long long)K << 32) | c;
            }
        }
        __syncthreads();
    }
    if (tid == 0) {
        g_meta[img * 32] = selCnt;
        g_maxb[img * 32] = 0u;
        g_thrK[img * 32] = K;
    }
}

// -------------------------------- k_decode ---------------------------------
__device__ __forceinline__ float4 decode_box(
    int img, unsigned flat,
    const float* b0p, const float* b1p, const float* b2p,
    const float* b3p, const float* b4p,
    const float* __restrict__ anchors, float limx, float limy) {
    unsigned anchor = flat / (unsigned)NCLS;
    int lvl, lf, off;
    if (anchor < 36864u)      { lvl = 0; lf = 6; off = 0; }
    else if (anchor < 46080u) { lvl = 1; lf = 5; off = 36864; }
    else if (anchor < 48384u) { lvl = 2; lf = 4; off = 46080; }
    else if (anchor < 48960u) { lvl = 3; lf = 3; off = 48384; }
    else                      { lvl = 4; lf = 2; off = 48960; }
    int f = 1 << lf;
    int p = (int)anchor - off;
    int a = p % 9;
    int cell = p / 9;
    int y = cell >> lf;
    int x = cell & (f - 1);
    const float* bt = (lvl == 0) ? b0p : (lvl == 1) ? b1p : (lvl == 2) ? b2p
                     : (lvl == 3) ? b3p : b4p;
    size_t ffs = (size_t)f * f;
    size_t base = (((size_t)img * 36 + a * 4) << (2 * lf)) + (y << lf) + x;
    float ty = bt[base];
    float tx = bt[base + ffs];
    float th = bt[base + 2 * ffs];
    float tw = bt[base + 3 * ffs];
    float ay1 = anchors[anchor * 4 + 0];
    float ax1 = anchors[anchor * 4 + 1];
    float ay2 = anchors[anchor * 4 + 2];
    float ax2 = anchors[anchor * 4 + 3];
    float ha = ay2 - ay1, wa = ax2 - ax1;
    float yca = (ay1 + ay2) * 0.5f, xca = (ax1 + ax2) * 0.5f;
    float w = expf(tw) * wa;
    float h = expf(th) * ha;
    float yc = ty * ha + yca;
    float xc = tx * wa + xca;
    float x1 = xc - w * 0.5f, y1 = yc - h * 0.5f;
    float x2 = xc + w * 0.5f, y2 = yc + h * 0.5f;
    x1 = fminf(fmaxf(x1, 0.0f), limx);
    y1 = fminf(fmaxf(y1, 0.0f), limy);
    x2 = fminf(fmaxf(x2, 0.0f), limx);
    y2 = fminf(fmaxf(y2, 0.0f), limy);
    return make_float4(x1, y1, x2, y2);
}

extern "C" __global__ void __launch_bounds__(1024)
k_decode(const float* __restrict__ boxL0, const float* __restrict__ boxL1,
         const float* __restrict__ boxL2, const float* __restrict__ boxL3,
         const float* __restrict__ boxL4, const float* __restrict__ anchors,
         const float* __restrict__ scales, const float* __restrict__ sizesp) {
    const int img = blockIdx.y;
    int N = g_meta[img * 32];
    if (N > SLOTS) N = SLOTS;
    const int i = blockIdx.x * 1024 + threadIdx.x;
    float mxv = 0.0f;
    if (i < N) {
        unsigned long long e = g_sel[(size_t)img * SLOTS + i];
        unsigned key = (unsigned)(e >> 32);
        unsigned c = (unsigned)e;
        unsigned flat = g_idx[(size_t)img * CAP + c];
        float scale = scales[img];
        float limx = sizesp[img * 2 + 0] / scale;
        float limy = sizesp[img * 2 + 1] / scale;
        float4 rb = decode_box(img, flat, boxL0, boxL1, boxL2, boxL3, boxL4,
                               anchors, limx, limy);
        g_box[(size_t)img * SLOTS + i] = rb;
        g_rank[(size_t)img * SLOTS + i] =
            ((unsigned long long)key << 32) | (unsigned)(~flat);
        mxv = fmaxf(fmaxf(rb.x, rb.y), fmaxf(rb.z, rb.w));
    }
#pragma unroll
    for (int o = 16; o; o >>= 1)
        mxv = fmaxf(mxv, __shfl_down_sync(0xffffffffu, mxv, o));
    if ((threadIdx.x & 31) == 0 && mxv > 0.0f)
        atomicMax(&g_maxb[img * 32], __float_as_uint(mxv));
}

// -------------------------------- k_nms ------------------------------------
__device__ __forceinline__ void write_det(float* out, int img, int row,
                                          unsigned long long rv, float4 raw,
                                          float scale) {
    unsigned key = (unsigned)(rv >> 32);
    unsigned flat = ~(unsigned)rv;
    unsigned uk = (key & 0x80000000u) ? (key & 0x7fffffffu) : ~key;
    float v = __uint_as_float(uk);
    float sc = 1.0f / (1.0f + expf(-v));
    float b0 = raw.x * scale, b1 = raw.y * scale;
    float b2 = raw.z * scale, b3 = raw.w * scale;
    float* o2 = out + ((size_t)img * NDET + row) * 6;
    o2[0] = b0;
    o2[1] = b1;
    o2[2] = b2 - b0;
    o2[3] = b3 - b1;
    o2[4] = sc;
    o2[5] = (float)(flat % (unsigned)NCLS) + 1.0f;
}

__device__ __forceinline__ bool iou_sup(float4 cb, float arJ, float4 kb,
                                        float kbA) {
    float ix1 = fmaxf(cb.x, kb.x), iy1 = fmaxf(cb.y, kb.y);
    float ix2 = fminf(cb.z, kb.z), iy2 = fminf(cb.w, kb.w);
    float inter = fmaxf(ix2 - ix1, 0.0f) * fmaxf(iy2 - iy1, 0.0f);
    float iou = inter / (arJ + kbA - inter);
    return !(iou <= 0.5f);
}

// smem layout offsets (bytes), GCAP = 1024
#define NMS_LO 0            // unsigned [SLOTS]        20096
#define NMS_HI 20096        // unsigned [SLOTS]        20096
#define NMS_A 40192         // u64 [GCAP]              8192
#define NMS_SLOT 48384      // unsigned [GCAP]         4096
#define NMS_RAW 52480       // float4 [GCAP]           16384
#define NMS_OFF 68864       // float4 [GCAP]           16384
#define NMS_AR 85248        // float [GCAP]            4096
#define NMS_KB 89344        // float4 [NDET]           1600
#define NMS_KBA 90944       // float [NDET]            400
#define NMS_KL 91344        // unsigned [NDET]         400
#define NMS_ROWC 91744      // unsigned [64*2]         512
#define NMS_PREC 92256      // unsigned [2+pad]        32
#define NMS_HIST 92288      // unsigned [NBINS]        16384
#define NMS_SMEM 108672

extern "C" __global__ void __launch_bounds__(1024, 1)
k_nms(const float* __restrict__ scales, float* __restrict__ out) {
    extern __shared__ char smb[];
    unsigned* sLo = (unsigned*)(smb + NMS_LO);
    unsigned* sHi = (unsigned*)(smb + NMS_HI);
    unsigned long long* sA = (unsigned long long*)(smb + NMS_A);
    unsigned* gSlot = (unsigned*)(smb + NMS_SLOT);
    float4* sRaw = (float4*)(smb + NMS_RAW);
    float4* sOff = (float4*)(smb + NMS_OFF);
    float* sAr = (float*)(smb + NMS_AR);
    float4* kb = (float4*)(smb + NMS_KB);
    float* kbA = (float*)(smb + NMS_KBA);
    unsigned* keptList = (unsigned*)(smb + NMS_KL);
    unsigned* sRowC = (unsigned*)(smb + NMS_ROWC);
    unsigned* sPreC = (unsigned*)(smb + NMS_PREC);
    unsigned* sHist = (unsigned*)(smb + NMS_HIST);

    __shared__ unsigned long long sWS[64];
    __shared__ int redW[32];
    __shared__ int sRed;
    __shared__ int sChosen, sAbove;
    __shared__ int gCnt2;
    __shared__ int sKcnt;
    __shared__ int sKeptTot;

    const int img = blockIdx.x;
    const int tid = threadIdx.x;
    const int lane = tid & 31;
    const int wid = tid >> 5;
    const unsigned lt = (1u << lane) - 1u;

    int N = g_meta[img * 32];
    if (N > SLOTS) N = SLOTS;
    const unsigned long long* grk = &g_rank[(size_t)img * SLOTS];
    const float4* gbx = &g_box[(size_t)img * SLOTS];
    const float scale = scales[img];
    const float M = __uint_as_float(g_maxb[img * 32]) + 1.0f;
    unsigned Kb = g_thrK[img * 32];
    if (Kb < 1u) Kb = 1u;
    const unsigned maxK = g_maxk[img * 32];

    if (tid == 0) sKeptTot = 0;
    for (int i = tid; i < SLOTS; i += 1024) {
        unsigned long long r = (i < N) ? grk[i] : 0ull;
        sLo[i] = (unsigned)r;
        sHi[i] = (unsigned)(r >> 32);
    }
    __syncthreads();

    unsigned prevThr = 0xFFFFFFFFu;
    int hShift = 0;
    bool histValid = false;

    for (int w = 0; w < 16; w++) {
        // ---- count remaining (window 0: trivially N) ----
        int rem;
        if (w == 0) {
            rem = N;
        } else {
            int cnt = 0;
            for (int i = tid; i < SLOTS; i += 1024) {
                unsigned h = sHi[i];
                cnt += (h >= 1u && h < prevThr) ? 1 : 0;
            }
#pragma unroll
            for (int o = 16; o; o >>= 1)
                cnt += __shfl_down_sync(0xffffffffu, cnt, o);
            if (lane == 0) redW[wid] = cnt;
            __syncthreads();
            if (tid == 0) {
                int s = 0;
                for (int ww = 0; ww < 32; ww++) s += redW[ww];
                sRed = s;
            }
            __syncthreads();
            rem = sRed;
        }
        if (rem == 0) break;

        // ---- window threshold ----
        unsigned thrH = 1u;
        bool needExact = false;
        if (rem > GTARGET) {
            if (w == 0 && maxK >= Kb) {
                // fast path: adaptive histogram over (hi - Kb) >> shift
                unsigned range = maxK - Kb + 1u;
                int shift = 0;
                while ((range >> shift) >= (unsigned)NBINS) shift++;
                hShift = shift;
                for (int b = tid; b < NBINS; b += 1024) sHist[b] = 0u;
                __syncthreads();
                for (int i = tid; i < SLOTS; i += 1024) {
                    unsigned h = sHi[i];
                    if (h >= Kb) atomicAdd(&sHist[(h - Kb) >> shift], 1u);
                }
                __syncthreads();
                // suffix-count scan: largest bin b* with C(b*) >= GTARGET
                int s = (int)(sHist[tid * 4] + sHist[tid * 4 + 1] +
                              sHist[tid * 4 + 2] + sHist[tid * 4 + 3]);
                int incl = s;
#pragma unroll
                for (int o = 1; o < 32; o <<= 1) {
                    int v2 = __shfl_up_sync(0xffffffffu, incl, o);
                    if (lane >= o) incl += v2;
                }
                if (lane == 31) redW[wid] = incl;
                __syncthreads();
                if (wid == 0) {
                    int v2 = redW[lane];
                    int wincl = v2;
#pragma unroll
                    for (int o = 1; o < 32; o <<= 1) {
                        int u2 = __shfl_up_sync(0xffffffffu, wincl, o);
                        if (lane >= o) wincl += u2;
                    }
                    redW[lane] = wincl;
                }
                __syncthreads();
                int warpOff = (wid == 0) ? 0 : redW[wid - 1];
                int prefIncl = warpOff + incl;
                int total = redW[31];
                int S_t = total - (prefIncl - s);
                int S_next = total - prefIncl;
                if (S_t >= GTARGET && S_next < GTARGET) {
                    int Cc = S_next;
                    int bstar = tid * 4;
                    for (int b = tid * 4 + 3; b >= tid * 4; b--) {
                        Cc += (int)sHist[b];
                        if (Cc >= GTARGET) { bstar = b; break; }
                    }
                    sChosen = bstar;
                }
                __syncthreads();
                thrH = Kb + ((unsigned)sChosen << shift);
                histValid = true;
            } else if (histValid) {
                // reuse window-0 histogram: k = GTARGET*(w+1)
                int ktarget = GTARGET * (w + 1);
                if (ktarget >= N) {
                    thrH = 1u;
                } else {
                    int s = (int)(sHist[tid * 4] + sHist[tid * 4 + 1] +
                                  sHist[tid * 4 + 2] + sHist[tid * 4 + 3]);
                    int incl = s;
#pragma unroll
                    for (int o = 1; o < 32; o <<= 1) {
                        int v2 = __shfl_up_sync(0xffffffffu, incl, o);
                        if (lane >= o) incl += v2;
                    }
                    if (lane == 31) redW[wid] = incl;
                    __syncthreads();
                    if (wid == 0) {
                        int v2 = redW[lane];
                        int wincl = v2;
#pragma unroll
                        for (int o = 1; o < 32; o <<= 1) {
                            int u2 = __shfl_up_sync(0xffffffffu, wincl, o);
                            if (lane >= o) wincl += u2;
                        }
                        redW[lane] = wincl;
                    }
                    __syncthreads();
                    int warpOff = (wid == 0) ? 0 : redW[wid - 1];
                    int prefIncl = warpOff + incl;
                    int total = redW[31];
                    int S_t = total - (prefIncl - s);
                    int S_next = total - prefIncl;
                    if (S_t >= ktarget && S_next < ktarget) {
                        int Cc = S_next;
                        int bstar = tid * 4;
                        for (int b = tid * 4 + 3; b >= tid * 4; b--) {
                            Cc += (int)sHist[b];
                            if (Cc >= ktarget) { bstar = b; break; }
                        }
                        sChosen = bstar;
                    }
                    __syncthreads();
                    if (total < ktarget) thrH = 1u;
                    else thrH = Kb + ((unsigned)sChosen << hShift);
                    if (thrH >= prevThr) needExact = true;  // degenerate bin
                }
            } else {
                needExact = true;
            }
        }

        // ---- gather + (rare) exact-search retry on overflow ----
        int Gc = 0;
        for (int attempt = 0; attempt < 2; attempt++) {
            if (needExact) {
                unsigned pm = 0, pv = 0;
                int k = GTARGET;
                for (int sh = 30; sh >= 0; sh -= 3) {
                    unsigned long long c64 = 0;
                    for (int i = tid; i < SLOTS; i += 1024) {
                        unsigned h = sHi[i];
                        if (h >= 1u && h < prevThr && (h & pm) == pv)
                            c64 += 1ull << (((h >> sh) & 7u) * 8);
                    }
                    unsigned long long lo = spread4((unsigned)c64);
                    unsigned long long hi = spread4((unsigned)(c64 >> 32));
#pragma unroll
                    for (int o = 16; o; o >>= 1) {
                        lo += __shfl_down_sync(0xffffffffu, lo, o);
                        hi += __shfl_down_sync(0xffffffffu, hi, o);
                    }
                    if (lane == 0) { sWS[wid * 2] = lo; sWS[wid * 2 + 1] = hi; }
                    __syncthreads();
                    if (wid == 0) {
                        lo = sWS[lane * 2];
                        hi = sWS[lane * 2 + 1];
#pragma unroll
                        for (int o = 16; o; o >>= 1) {
                            lo += __shfl_down_sync(0xffffffffu, lo, o);
                            hi += __shfl_down_sync(0xffffffffu, hi, o);
                        }
                        if (lane == 0) {
                            unsigned cnt[8];
                            cnt[0] = (unsigned)(lo & 0xFFFF);
                            cnt[1] = (unsigned)((lo >> 16) & 0xFFFF);
                            cnt[2] = (unsigned)((lo >> 32) & 0xFFFF);
                            cnt[3] = (unsigned)((lo >> 48) & 0xFFFF);
                            cnt[4] = (unsigned)(hi & 0xFFFF);
                            cnt[5] = (unsigned)((hi >> 16) & 0xFFFF);
                            cnt[6] = (unsigned)((hi >> 32) & 0xFFFF);
                            cnt[7] = (unsigned)((hi >> 48) & 0xFFFF);
                            unsigned cum = 0;
                            int ch = 0;
                            unsigned ab = 0;
                            for (int b = 7; b >= 0; b--) {
                                if (cum + cnt[b] >= (unsigned)k) { ch = b; ab = cum; break; }
                                cum += cnt[b];
                            }
                            sChosen = ch;
                            sAbove = (int)ab;
                        }
                    }
                    __syncthreads();
                    pv |= ((unsigned)sChosen) << sh;
                    pm |= 7u << sh;
                    k -= sAbove;
                }
                thrH = pv;
            }
            // gather window [thrH, prevThr)
            if (tid == 0) gCnt2 = 0;
            if (tid < GCAP) sA[tid] = 0ull;
            __syncthreads();
            for (int i = tid; i < SLOTS; i += 1024) {
                unsigned h = sHi[i];
                bool take = (h >= thrH) && (h < prevThr);
                unsigned m = __ballot_sync(0xffffffffu, take);
                if (m) {
                    int leader = __ffs(m) - 1;
                    unsigned base = 0;
                    if (lane == leader)
                        base = (unsigned)atomicAdd(&gCnt2, __popc(m));
                    base = __shfl_sync(0xffffffffu, base, leader);
                    if (take) {
                        unsigned pos = base + (unsigned)__popc(m & lt);
                        if (pos < GCAP) {
                            sA[pos] = ((unsigned long long)h << 32) | sLo[i];
                            gSlot[pos] = (unsigned)i;
                        }
                    }
                }
            }
            __syncthreads();
            Gc = gCnt2;
            if (Gc <= GCAP || needExact) break;
            needExact = true;  // histogram bin overflowed: redo exactly
        }
        if (Gc > GCAP) Gc = GCAP;  // needs 75+ identical float keys: impossible

        if (Gc > 0) {
            // ---- bitonic sort GCAP entries, descending ----
            for (int k2 = 2; k2 <= GCAP; k2 <<= 1) {
                for (int j = k2 >> 1; j > 0; j >>= 1) {
                    int i = tid;
                    int ixj = i ^ j;
                    if (i < GCAP && ixj > i) {
                        bool up = ((i & k2) == 0);
                        unsigned long long a = sA[i], b2 = sA[ixj];
                        bool sw = up ? (a < b2) : (a > b2);
                        if (sw) {
                            sA[i] = b2;
                            sA[ixj] = a;
                            unsigned t = gSlot[i];
                            gSlot[i] = gSlot[ixj];
                            gSlot[ixj] = t;
                        }
                    }
                    __syncthreads();
                }
            }

            // ---- fetch boxes ----
            if (tid < GCAP) {
                unsigned long long rv = sA[tid];
                float4 raw = make_float4(0.f, 0.f, 0.f, 0.f);
                float4 ofb = raw;
                float ar = 0.f;
                if (rv != 0ull) {
                    raw = gbx[gSlot[tid]];
                    float off = (float)((~(unsigned)rv) % (unsigned)NCLS) * M;
                    ofb = make_float4(raw.x + off, raw.y + off, raw.z + off,
                                      raw.w + off);
                    ar = (ofb.z - ofb.x) * (ofb.w - ofb.y);
                }
                sRaw[tid] = raw;
                sOff[tid] = ofb;
                sAr[tid] = ar;
            }
            __syncthreads();

            // ---- lazy chunked greedy resolve (chunks of 64) ----
            for (int cbs = 0; cbs < Gc; cbs += 64) {
                int keptTot = sKeptTot;
                if (keptTot >= NDET) break;
                int ccnt = Gc - cbs;
                if (ccnt > 64) ccnt = 64;
                if (tid < 128) sRowC[tid] = 0u;
                else if (tid < 130) sPreC[tid - 128] = 0u;
                __syncthreads();
                {
                    int c = tid >> 4;
                    int sub = tid & 15;
                    if (c < ccnt) {
                        int j = cbs + c;
                        float4 q = sOff[j];
                        float aq = sAr[j];
                        bool dead = false;
                        for (int k2 = sub; k2 < keptTot; k2 += 16)
                            dead |= iou_sup(q, aq, kb[k2], kbA[k2]);
                        if (dead) atomicOr(&sPreC[c >> 5], 1u << (c & 31));
                        unsigned w0 = 0, w1 = 0;
                        for (int k2 = sub; k2 < ccnt; k2 += 16) {
                            if (k2 > c &&
                                iou_sup(q, aq, sOff[cbs + k2], sAr[cbs + k2])) {
                                if (k2 < 32) w0 |= 1u << k2;
                                else w1 |= 1u << (k2 - 32);
                            }
                        }
                        if (w0) atomicOr(&sRowC[c * 2], w0);
                        if (w1) atomicOr(&sRowC[c * 2 + 1], w1);
                    }
                }
                __syncthreads();
                if (tid == 0) {
                    unsigned d0 = sPreC[0], d1 = sPreC[1];
                    int kcnt = 0;
                    for (int c = 0; c < ccnt && keptTot + kcnt < NDET; c++) {
                        bool dead = (c < 32) ? ((d0 >> c) & 1u)
                                             : ((d1 >> (c - 32)) & 1u);
                        if (!dead) {
                            keptList[kcnt++] = (unsigned)(cbs + c);
                            d0 |= sRowC[c * 2];
                            d1 |= sRowC[c * 2 + 1];
                        }
                    }
                    sKcnt = kcnt;
                }
                __syncthreads();
                int kcnt = sKcnt;
                if (tid < kcnt) {
                    int j = (int)keptList[tid];
                    int row = keptTot + tid;
                    write_det(out, img, row, sA[j], sRaw[j], scale);
                    kb[row] = sOff[j];
                    kbA[row] = sAr[j];
                }
                __syncthreads();
                if (tid == 0) sKeptTot = keptTot + kcnt;
                __syncthreads();
            }
        }

        prevThr = thrH;
        __syncthreads();
        if (sKeptTot >= NDET || thrH == 1u) break;
    }

    // ---- zero-fill remaining rows + reset counter for next call ----
    int rows = sKeptTot;
    float* o2 = out + ((size_t)img * NDET + rows) * 6;
    for (int t = tid; t < (NDET - rows) * 6; t += 1024) o2[t] = 0.0f;
    if (tid == 0) g_cnt[img * 32] = 0;
}

// ---------------------------------------------------------------------------
extern "C" void kernel_launch(void* const* d_in, const int* in_sizes, int n_in,
                              void* d_out, int out_size) {
    static const int feats[5] = {64, 32, 16, 8, 4};
    const float* cls[5] = {0, 0, 0, 0, 0};
    const float* box[5] = {0, 0, 0, 0, 0};
    const float* anchors = 0;
    const float* scales = 0;
    const float* sizesp = 0;

    for (int j = 0; j < n_in; j++) {
        long sz = in_sizes[j];
        const float* p = (const float*)d_in[j];
        if (sz == 49104L * 4) anchors = p;
        else if (sz == 16) scales = p;
        else if (sz == 32) sizesp = p;
        else {
            for (int i = 0; i < 5; i++) {
                long ff = (long)feats[i] * feats[i];
                if (sz == 16L * 810 * ff) cls[i] = p;
                else if (sz == 16L * 36 * ff) box[i] = p;
            }
        }
    }

    dim3 gc(542, NIMG);
    k_collect<<<gc, 256>>>((const float4*)cls[0], (const float4*)cls[1],
                           (const float4*)cls[2], (const float4*)cls[3],
                           (const float4*)cls[4]);

    cudaFuncSetAttribute((const void*)k_sel,
                         cudaFuncAttributeMaxDynamicSharedMemorySize,
                         SKEY_CAP * 4);
    k_sel<<<NIMG, 1024, SKEY_CAP * 4>>>();

    dim3 gd(5, NIMG);
    k_decode<<<gd, 1024>>>(box[0], box[1], box[2], box[3], box[4], anchors,
                           scales, sizesp);

    cudaFuncSetAttribute((const void*)k_nms,
                         cudaFuncAttributeMaxDynamicSharedMemorySize,
                         NMS_SMEM);
    k_nms<<<NIMG, 1024, NMS_SMEM>>>(scales, (float*)d_out);
}

// round 16
// speedup vs baseline: 1.0411x; 1.0411x over previous
#include <cuda_runtime.h>
#include <cuda_bf16.h>
#include <math.h>

// ---------------------------------------------------------------------------
// DetBenchPredict: EfficientDet postprocess
//   B=16 images, 49104 anchors, 90 classes, top-5000, NMS(0.5) -> 100 dets
// ---------------------------------------------------------------------------

#define NIMG 16
#define NCLS 90
#define KSEL 5000
#define SLOTS 5024
#define CAP 65536
#define NDET 100
#define TCAP 1024
#define BCAP 512
#define SKEY_CAP 32768
#define GCAP 1024
#define GTARGET 950
#define NBINS 4096

// Device scratch (128B-strided counters -> separate L2 slices).
__device__ unsigned g_cnt[NIMG * 32];
__device__ unsigned g_key[(size_t)NIMG * CAP];
__device__ unsigned g_idx[(size_t)NIMG * CAP];
__device__ unsigned long long g_sel[(size_t)NIMG * SLOTS];
__device__ unsigned long long g_rank[(size_t)NIMG * SLOTS];
__device__ float4 g_box[(size_t)NIMG * SLOTS];
__device__ int g_meta[NIMG * 32];
__device__ unsigned g_maxb[NIMG * 32];
__device__ unsigned g_thrK[NIMG * 32];
__device__ unsigned g_maxk[NIMG * 32];

// -------------------------------- collect pass -----------------------------
__global__ void __launch_bounds__(256)
k_collect(const float4* __restrict__ c0, const float4* __restrict__ c1,
          const float4* __restrict__ c2, const float4* __restrict__ c3,
          const float4* __restrict__ c4) {
    __shared__ unsigned sCnt, sBase;
    __shared__ unsigned sKeyB[BCAP];
    __shared__ unsigned sIdxB[BCAP];

    const int img = blockIdx.y;
    const int b = blockIdx.x;
    const int tid = threadIdx.x;
    if (tid == 0) sCnt = 0;
    __syncthreads();

    const float4* p;
    int n4, lf, aOff, start;
    bool check;
    if (b < 405)      { p = c0; n4 = 829440; lf = 6; aOff = 0;     start = b * 2048;         check = false; }
    else if (b < 506) { p = c1; n4 = 207360; lf = 5; aOff = 36864; start = (b - 405) * 2048; check = false; }
    else if (b == 506){ p = c1; n4 = 207360; lf = 5; aOff = 36864; start = 206848;           check = true;  }
    else if (b < 532) { p = c2; n4 = 51840;  lf = 4; aOff = 46080; start = (b - 507) * 2048; check = false; }
    else if (b == 532){ p = c2; n4 = 51840;  lf = 4; aOff = 46080; start = 51200;            check = true;  }
    else if (b < 539) { p = c3; n4 = 12960;  lf = 3; aOff = 48384; start = (b - 533) * 2048; check = false; }
    else if (b == 539){ p = c3; n4 = 12960;  lf = 3; aOff = 48384; start = 12288;            check = true;  }
    else if (b == 540){ p = c4; n4 = 3240;   lf = 2; aOff = 48960; start = 0;                check = false; }
    else              { p = c4; n4 = 3240;   lf = 2; aOff = 48960; start = 2048;             check = true;  }

    p += (size_t)img * n4;
    const int i0 = start + tid;

    float4 v[8];
    if (!check) {
#pragma unroll
        for (int k = 0; k < 8; k++) v[k] = p[i0 + k * 256];
    } else {
#pragma unroll
        for (int k = 0; k < 8; k++) {
            int i = i0 + k * 256;
            v[k] = (i < n4) ? p[i] : make_float4(-9.f, -9.f, -9.f, -9.f);
        }
    }

    float mf = fmaxf(fmaxf(fmaxf(v[0].x, v[0].y), fmaxf(v[0].z, v[0].w)),
                     fmaxf(fmaxf(v[1].x, v[1].y), fmaxf(v[1].z, v[1].w)));
    mf = fmaxf(mf, fmaxf(fmaxf(fmaxf(v[2].x, v[2].y), fmaxf(v[2].z, v[2].w)),
                         fmaxf(fmaxf(v[3].x, v[3].y), fmaxf(v[3].z, v[3].w))));
    unsigned mu = min(min(min(__float_as_uint(v[4].x), __float_as_uint(v[4].y)),
                          min(__float_as_uint(v[4].z), __float_as_uint(v[4].w))),
                      min(min(__float_as_uint(v[5].x), __float_as_uint(v[5].y)),
                          min(__float_as_uint(v[5].z), __float_as_uint(v[5].w))));
    mu = min(mu,
             min(min(min(__float_as_uint(v[6].x), __float_as_uint(v[6].y)),
                     min(__float_as_uint(v[6].z), __float_as_uint(v[6].w))),
                 min(min(__float_as_uint(v[7].x), __float_as_uint(v[7].y)),
                     min(__float_as_uint(v[7].z), __float_as_uint(v[7].w)))));
    bool hit = (mf > -1.5f) || (mu < 0xBFC00000u);

    if (__ballot_sync(0xffffffffu, hit)) {
        if (hit) {
            const int f = 1 << lf;
            const int ff = 1 << (2 * lf);
#pragma unroll
            for (int k = 0; k < 8; k++) {
                int i = i0 + k * 256;
                float vs[4] = {v[k].x, v[k].y, v[k].z, v[k].w};
#pragma unroll
                for (int j = 0; j < 4; j++) {
                    if (vs[j] > -1.5f) {
                        int t = i * 4 + j;
                        int ch = t >> (2 * lf);
                        int r = t & (ff - 1);
                        int y = r >> lf;
                        int x = r & (f - 1);
                        int a = ch / NCLS;
                        int c = ch - a * NCLS;
                        unsigned flat =
                            (unsigned)((aOff + (y * f + x) * 9 + a) * NCLS + c);
                        unsigned u = __float_as_uint(vs[j]);
                        unsigned key = (u & 0x80000000u) ? ~u : (u | 0x80000000u);
                        unsigned pos = atomicAdd(&sCnt, 1u);
                        if (pos < BCAP) {
                            sKeyB[pos] = key;
                            sIdxB[pos] = flat;
                        } else {
                            unsigned g = atomicAdd(&g_cnt[img * 32], 1u);
                            if (g < CAP) {
                                g_key[(size_t)img * CAP + g] = key;
                                g_idx[(size_t)img * CAP + g] = flat;
                            }
                        }
                    }
                }
            }
        }
    }
    __syncthreads();
    unsigned n = sCnt;
    if (n > BCAP) n = BCAP;
    if (tid == 0 && n) sBase = atomicAdd(&g_cnt[img * 32], n);
    __syncthreads();
    if (n) {
        unsigned base = sBase;
        for (unsigned i = tid; i < n; i += 256) {
            unsigned pos = base + i;
            if (pos < CAP) {
                g_key[(size_t)img * CAP + pos] = sKeyB[i];
                g_idx[(size_t)img * CAP + pos] = sIdxB[i];
            }
        }
    }
}

// spread 4 bytes into 16-bit fields of a u64
__device__ __forceinline__ unsigned long long spread4(unsigned x) {
    unsigned long long t = x;
    t = (t | (t << 16)) & 0x0000FFFF0000FFFFull;
    t = (t | (t << 8)) & 0x00FF00FF00FF00FFull;
    return t;
}

// -------------------------------- k_sel ------------------------------------
extern "C" __global__ void __launch_bounds__(1024, 1) k_sel() {
    extern __shared__ unsigned sKeys[];
    __shared__ unsigned tieIdx[TCAP];
    __shared__ unsigned long long sWS[64];
    __shared__ unsigned redM[32];
    __shared__ unsigned tieCnt;
    __shared__ int selCnt;
    __shared__ int sChosen, sAbove;

    const int img = blockIdx.x;
    const int tid = threadIdx.x;
    const int lane = tid & 31;
    const int wid = tid >> 5;
    const unsigned lt = (1u << lane) - 1u;

    unsigned C = g_cnt[img * 32];
    if (C > CAP) C = CAP;
    const unsigned* keys = &g_key[(size_t)img * CAP];
    const unsigned* idxs = &g_idx[(size_t)img * CAP];
    if (tid == 0) { tieCnt = 0; selCnt = 0; }

    const unsigned S = C < SKEY_CAP ? C : SKEY_CAP;
    unsigned mk = 0;
    for (unsigned c = tid; c < S; c += 1024) {
        unsigned k = keys[c];
        sKeys[c] = k;
        mk = max(mk, k);
    }
    for (unsigned c = S + tid; c < C; c += 1024) mk = max(mk, keys[c]);
    const int S4 = (int)((S + 3) >> 2);
    for (unsigned c = S + tid; c < (unsigned)(S4 * 4); c += 1024) sKeys[c] = 0;
#pragma unroll
    for (int o = 16; o; o >>= 1)
        mk = max(mk, __shfl_down_sync(0xffffffffu, mk, o));
    if (lane == 0) redM[wid] = mk;
    __syncthreads();
    if (tid == 0) {
        unsigned m = 0;
        for (int w = 0; w < 32; w++) m = max(m, redM[w]);
        g_maxk[img * 32] = m;
    }

    unsigned K = 0;
    int needEq = 0;
    const bool selectAll = (C <= KSEL);
    if (!selectAll) {
        unsigned pm = 0, pv = 0;
        int k = KSEL;
        const uint4* k4 = (const uint4*)sKeys;
        for (int sh = 30; sh >= 0; sh -= 3) {
            unsigned long long c64 = 0;
            for (int i = tid; i < S4; i += 1024) {
                uint4 kk = k4[i];
                if ((kk.x & pm) == pv) c64 += 1ull << (((kk.x >> sh) & 7u) * 8);
                if ((kk.y & pm) == pv) c64 += 1ull << (((kk.y >> sh) & 7u) * 8);
                if ((kk.z & pm) == pv) c64 += 1ull << (((kk.z >> sh) & 7u) * 8);
                if ((kk.w & pm) == pv) c64 += 1ull << (((kk.w >> sh) & 7u) * 8);
            }
            for (unsigned c = S + tid; c < C; c += 1024) {
                unsigned kk = keys[c];
                if ((kk & pm) == pv) c64 += 1ull << (((kk >> sh) & 7u) * 8);
            }
            unsigned long long lo = spread4((unsigned)c64);
            unsigned long long hi = spread4((unsigned)(c64 >> 32));
#pragma unroll
            for (int o = 16; o; o >>= 1) {
                lo += __shfl_down_sync(0xffffffffu, lo, o);
                hi += __shfl_down_sync(0xffffffffu, hi, o);
            }
            if (lane == 0) { sWS[wid * 2] = lo; sWS[wid * 2 + 1] = hi; }
            __syncthreads();
            if (wid == 0) {
                lo = sWS[lane * 2];
                hi = sWS[lane * 2 + 1];
#pragma unroll
                for (int o = 16; o; o >>= 1) {
                    lo += __shfl_down_sync(0xffffffffu, lo, o);
                    hi += __shfl_down_sync(0xffffffffu, hi, o);
                }
                if (lane == 0) {
                    unsigned cnt[8];
                    cnt[0] = (unsigned)(lo & 0xFFFF);
                    cnt[1] = (unsigned)((lo >> 16) & 0xFFFF);
                    cnt[2] = (unsigned)((lo >> 32) & 0xFFFF);
                    cnt[3] = (unsigned)((lo >> 48) & 0xFFFF);
                    cnt[4] = (unsigned)(hi & 0xFFFF);
                    cnt[5] = (unsigned)((hi >> 16) & 0xFFFF);
                    cnt[6] = (unsigned)((hi >> 32) & 0xFFFF);
                    cnt[7] = (unsigned)((hi >> 48) & 0xFFFF);
                    unsigned cum = 0;
                    int ch = 0;
                    unsigned ab = 0;
                    for (int b = 7; b >= 0; b--) {
                        if (cum + cnt[b] >= (unsigned)k) { ch = b; ab = cum; break; }
                        cum += cnt[b];
                    }
                    sChosen = ch;
                    sAbove = (int)ab;
                }
            }
            __syncthreads();
            pv |= ((unsigned)sChosen) << sh;
            pm |= 7u << sh;
            k -= sAbove;
        }
        K = pv;
        needEq = k;
    }
    __syncthreads();

    unsigned long long* sel = &g_sel[(size_t)img * SLOTS];
    const unsigned Cr = ((C + 1023u) / 1024u) * 1024u;
    for (unsigned c = tid; c < Cr; c += 1024) {
        bool inb = c < C;
        unsigned key = inb ? (c < S ? sKeys[c] : keys[c]) : 0u;
        bool take = inb && (selectAll || key > K);
        bool tie = inb && !selectAll && (key == K);
        unsigned m = __ballot_sync(0xffffffffu, take);
        if (m) {
            int leader = __ffs(m) - 1;
            unsigned base = 0;
            if (lane == leader) base = (unsigned)atomicAdd(&selCnt, __popc(m));
            base = __shfl_sync(0xffffffffu, base, leader);
            if (take) {
                unsigned pos = base + (unsigned)__popc(m & lt);
                if (pos < SLOTS)
                    sel[pos] = ((unsigned long long)key << 32) | c;
            }
        }
        if (tie) {
            unsigned tp = atomicAdd(&tieCnt, 1u);
            if (tp < TCAP) tieIdx[tp] = c;
        }
    }
    __syncthreads();

    if (!selectAll) {
        int mt = tieCnt < TCAP ? (int)tieCnt : TCAP;
        for (int t = tid; t < mt; t += 1024) {
            unsigned c = tieIdx[t];
            unsigned my = idxs[c];
            int r = 0;
            for (int j = 0; j < mt; j++) r += (idxs[tieIdx[j]] < my) ? 1 : 0;
            if (r < needEq) {
                int pos = atomicAdd(&selCnt, 1);
                if (pos < SLOTS)
                    sel[pos] = ((unsigned long long)K << 32) | c;
            }
        }
        __syncthreads();
    }
    if (tid == 0) {
        g_meta[img * 32] = selCnt;
        g_maxb[img * 32] = 0u;
        g_thrK[img * 32] = K;
    }
}

// -------------------------------- k_decode ---------------------------------
__device__ __forceinline__ float4 decode_box(
    int img, unsigned flat,
    const float* b0p, const float* b1p, const float* b2p,
    const float* b3p, const float* b4p,
    const float* __restrict__ anchors, float limx, float limy) {
    unsigned anchor = flat / (unsigned)NCLS;
    int lvl, lf, off;
    if (anchor < 36864u)      { lvl = 0; lf = 6; off = 0; }
    else if (anchor < 46080u) { lvl = 1; lf = 5; off = 36864; }
    else if (anchor < 48384u) { lvl = 2; lf = 4; off = 46080; }
    else if (anchor < 48960u) { lvl = 3; lf = 3; off = 48384; }
    else                      { lvl = 4; lf = 2; off = 48960; }
    int f = 1 << lf;
    int p = (int)anchor - off;
    int a = p % 9;
    int cell = p / 9;
    int y = cell >> lf;
    int x = cell & (f - 1);
    const float* bt = (lvl == 0) ? b0p : (lvl == 1) ? b1p : (lvl == 2) ? b2p
                     : (lvl == 3) ? b3p : b4p;
    size_t ffs = (size_t)f * f;
    size_t base = (((size_t)img * 36 + a * 4) << (2 * lf)) + (y << lf) + x;
    float ty = bt[base];
    float tx = bt[base + ffs];
    float th = bt[base + 2 * ffs];
    float tw = bt[base + 3 * ffs];
    float ay1 = anchors[anchor * 4 + 0];
    float ax1 = anchors[anchor * 4 + 1];
    float ay2 = anchors[anchor * 4 + 2];
    float ax2 = anchors[anchor * 4 + 3];
    float ha = ay2 - ay1, wa = ax2 - ax1;
    float yca = (ay1 + ay2) * 0.5f, xca = (ax1 + ax2) * 0.5f;
    float w = expf(tw) * wa;
    float h = expf(th) * ha;
    float yc = ty * ha + yca;
    float xc = tx * wa + xca;
    float x1 = xc - w * 0.5f, y1 = yc - h * 0.5f;
    float x2 = xc + w * 0.5f, y2 = yc + h * 0.5f;
    x1 = fminf(fmaxf(x1, 0.0f), limx);
    y1 = fminf(fmaxf(y1, 0.0f), limy);
    x2 = fminf(fmaxf(x2, 0.0f), limx);
    y2 = fminf(fmaxf(y2, 0.0f), limy);
    return make_float4(x1, y1, x2, y2);
}

extern "C" __global__ void __launch_bounds__(1024)
k_decode(const float* __restrict__ boxL0, const float* __restrict__ boxL1,
         const float* __restrict__ boxL2, const float* __restrict__ boxL3,
         const float* __restrict__ boxL4, const float* __restrict__ anchors,
         const float* __restrict__ scales, const float* __restrict__ sizesp) {
    const int img = blockIdx.y;
    int N = g_meta[img * 32];
    if (N > SLOTS) N = SLOTS;
    const int i = blockIdx.x * 1024 + threadIdx.x;
    float mxv = 0.0f;
    if (i < N) {
        unsigned long long e = g_sel[(size_t)img * SLOTS + i];
        unsigned key = (unsigned)(e >> 32);
        unsigned c = (unsigned)e;
        unsigned flat = g_idx[(size_t)img * CAP + c];
        float scale = scales[img];
        float limx = sizesp[img * 2 + 0] / scale;
        float limy = sizesp[img * 2 + 1] / scale;
        float4 rb = decode_box(img, flat, boxL0, boxL1, boxL2, boxL3, boxL4,
                               anchors, limx, limy);
        g_box[(size_t)img * SLOTS + i] = rb;
        g_rank[(size_t)img * SLOTS + i] =
            ((unsigned long long)key << 32) | (unsigned)(~flat);
        mxv = fmaxf(fmaxf(rb.x, rb.y), fmaxf(rb.z, rb.w));
    }
#pragma unroll
    for (int o = 16; o; o >>= 1)
        mxv = fmaxf(mxv, __shfl_down_sync(0xffffffffu, mxv, o));
    if ((threadIdx.x & 31) == 0 && mxv > 0.0f)
        atomicMax(&g_maxb[img * 32], __float_as_uint(mxv));
}

// -------------------------------- k_nms ------------------------------------
__device__ __forceinline__ void write_det(float* out, int img, int row,
                                          unsigned long long rv, float4 raw,
                                          float scale) {
    unsigned key = (unsigned)(rv >> 32);
    unsigned flat = ~(unsigned)rv;
    unsigned uk = (key & 0x80000000u) ? (key & 0x7fffffffu) : ~key;
    float v = __uint_as_float(uk);
    float sc = 1.0f / (1.0f + expf(-v));
    float b0 = raw.x * scale, b1 = raw.y * scale;
    float b2 = raw.z * scale, b3 = raw.w * scale;
    float* o2 = out + ((size_t)img * NDET + row) * 6;
    o2[0] = b0;
    o2[1] = b1;
    o2[2] = b2 - b0;
    o2[3] = b3 - b1;
    o2[4] = sc;
    o2[5] = (float)(flat % (unsigned)NCLS) + 1.0f;
}

__device__ __forceinline__ bool iou_sup(float4 cb, float arJ, float4 kb,
                                        float kbA) {
    float ix1 = fmaxf(cb.x, kb.x), iy1 = fmaxf(cb.y, kb.y);
    float ix2 = fminf(cb.z, kb.z), iy2 = fminf(cb.w, kb.w);
    float inter = fmaxf(ix2 - ix1, 0.0f) * fmaxf(iy2 - iy1, 0.0f);
    float iou = inter / (arJ + kbA - inter);
    return !(iou <= 0.5f);
}

// smem layout offsets (bytes), GCAP = 1024
#define NMS_LO 0            // unsigned [SLOTS]        20096
#define NMS_HI 20096        // unsigned [SLOTS]        20096
#define NMS_A 40192         // u64 [GCAP]              8192
#define NMS_SLOT 48384      // unsigned [GCAP]         4096
#define NMS_RAW 52480       // float4 [GCAP]           16384
#define NMS_OFF 68864       // float4 [GCAP]           16384
#define NMS_AR 85248        // float [GCAP]            4096
#define NMS_KB 89344        // float4 [NDET]           1600
#define NMS_KBA 90944       // float [NDET]            400
#define NMS_KL 91344        // unsigned [NDET]         400
#define NMS_ROWC 91744      // unsigned [64*2]         512
#define NMS_PREC 92256      // unsigned [2+pad]        32
#define NMS_HIST 92288      // unsigned [NBINS]        16384
#define NMS_SMEM 108672

extern "C" __global__ void __launch_bounds__(1024, 1)
k_nms(const float* __restrict__ scales, float* __restrict__ out) {
    extern __shared__ char smb[];
    unsigned* sLo = (unsigned*)(smb + NMS_LO);
    unsigned* sHi = (unsigned*)(smb + NMS_HI);
    unsigned long long* sA = (unsigned long long*)(smb + NMS_A);
    unsigned* gSlot = (unsigned*)(smb + NMS_SLOT);
    float4* sRaw = (float4*)(smb + NMS_RAW);
    float4* sOff = (float4*)(smb + NMS_OFF);
    float* sAr = (float*)(smb + NMS_AR);
    float4* kb = (float4*)(smb + NMS_KB);
    float* kbA = (float*)(smb + NMS_KBA);
    unsigned* keptList = (unsigned*)(smb + NMS_KL);
    unsigned* sRowC = (unsigned*)(smb + NMS_ROWC);
    unsigned* sPreC = (unsigned*)(smb + NMS_PREC);
    unsigned* sHist = (unsigned*)(smb + NMS_HIST);

    __shared__ unsigned long long sWS[64];
    __shared__ int redW[32];
    __shared__ int sRed;
    __shared__ int sChosen, sAbove;
    __shared__ int gCnt2;
    __shared__ int sKcnt;
    __shared__ int sKeptTot;

    const int img = blockIdx.x;
    const int tid = threadIdx.x;
    const int lane = tid & 31;
    const int wid = tid >> 5;
    const unsigned lt = (1u << lane) - 1u;

    int N = g_meta[img * 32];
    if (N > SLOTS) N = SLOTS;
    const unsigned long long* grk = &g_rank[(size_t)img * SLOTS];
    const float4* gbx = &g_box[(size_t)img * SLOTS];
    const float scale = scales[img];
    const float M = __uint_as_float(g_maxb[img * 32]) + 1.0f;
    unsigned Kb = g_thrK[img * 32];
    if (Kb < 1u) Kb = 1u;
    const unsigned maxK = g_maxk[img * 32];

    if (tid == 0) sKeptTot = 0;
    for (int i = tid; i < SLOTS; i += 1024) {
        unsigned long long r = (i < N) ? grk[i] : 0ull;
        sLo[i] = (unsigned)r;
        sHi[i] = (unsigned)(r >> 32);
    }
    __syncthreads();

    unsigned prevThr = 0xFFFFFFFFu;
    int hShift = 0;
    bool histValid = false;

    for (int w = 0; w < 16; w++) {
        // ---- count remaining (window 0: trivially N) ----
        int rem;
        if (w == 0) {
            rem = N;
        } else {
            int cnt = 0;
            for (int i = tid; i < SLOTS; i += 1024) {
                unsigned h = sHi[i];
                cnt += (h >= 1u && h < prevThr) ? 1 : 0;
            }
#pragma unroll
            for (int o = 16; o; o >>= 1)
                cnt += __shfl_down_sync(0xffffffffu, cnt, o);
            if (lane == 0) redW[wid] = cnt;
            __syncthreads();
            if (tid == 0) {
                int s = 0;
                for (int ww = 0; ww < 32; ww++) s += redW[ww];
                sRed = s;
            }
            __syncthreads();
            rem = sRed;
        }
        if (rem == 0) break;

        // ---- window threshold ----
        unsigned thrH = 1u;
        bool needExact = false;
        if (rem > GTARGET) {
            if (w == 0 && maxK >= Kb) {
                // fast path: adaptive histogram over (hi - Kb) >> shift
                unsigned range = maxK - Kb + 1u;
                int shift = 0;
                while ((range >> shift) >= (unsigned)NBINS) shift++;
                hShift = shift;
                for (int b = tid; b < NBINS; b += 1024) sHist[b] = 0u;
                __syncthreads();
                for (int i = tid; i < SLOTS; i += 1024) {
                    unsigned h = sHi[i];
                    if (h >= Kb) atomicAdd(&sHist[(h - Kb) >> shift], 1u);
                }
                __syncthreads();
                // suffix-count scan: largest bin b* with C(b*) >= GTARGET
                int s = (int)(sHist[tid * 4] + sHist[tid * 4 + 1] +
                              sHist[tid * 4 + 2] + sHist[tid * 4 + 3]);
                int incl = s;
#pragma unroll
                for (int o = 1; o < 32; o <<= 1) {
                    int v2 = __shfl_up_sync(0xffffffffu, incl, o);
                    if (lane >= o) incl += v2;
                }
                if (lane == 31) redW[wid] = incl;
                __syncthreads();
                if (wid == 0) {
                    int v2 = redW[lane];
                    int wincl = v2;
#pragma unroll
                    for (int o = 1; o < 32; o <<= 1) {
                        int u2 = __shfl_up_sync(0xffffffffu, wincl, o);
                        if (lane >= o) wincl += u2;
                    }
                    redW[lane] = wincl;
                }
                __syncthreads();
                int warpOff = (wid == 0) ? 0 : redW[wid - 1];
                int prefIncl = warpOff + incl;
                int total = redW[31];
                int S_t = total - (prefIncl - s);
                int S_next = total - prefIncl;
                if (S_t >= GTARGET && S_next < GTARGET) {
                    int Cc = S_next;
                    int bstar = tid * 4;
                    for (int b = tid * 4 + 3; b >= tid * 4; b--) {
                        Cc += (int)sHist[b];
                        if (Cc >= GTARGET) { bstar = b; break; }
                    }
                    sChosen = bstar;
                }
                __syncthreads();
                thrH = Kb + ((unsigned)sChosen << shift);
                histValid = true;
            } else if (histValid) {
                // reuse window-0 histogram: k = GTARGET*(w+1)
                int ktarget = GTARGET * (w + 1);
                if (ktarget >= N) {
                    thrH = 1u;
                } else {
                    int s = (int)(sHist[tid * 4] + sHist[tid * 4 + 1] +
                                  sHist[tid * 4 + 2] + sHist[tid * 4 + 3]);
                    int incl = s;
#pragma unroll
                    for (int o = 1; o < 32; o <<= 1) {
                        int v2 = __shfl_up_sync(0xffffffffu, incl, o);
                        if (lane >= o) incl += v2;
                    }
                    if (lane == 31) redW[wid] = incl;
                    __syncthreads();
                    if (wid == 0) {
                        int v2 = redW[lane];
                        int wincl = v2;
#pragma unroll
                        for (int o = 1; o < 32; o <<= 1) {
                            int u2 = __shfl_up_sync(0xffffffffu, wincl, o);
                            if (lane >= o) wincl += u2;
                        }
                        redW[lane] = wincl;
                    }
                    __syncthreads();
                    int warpOff = (wid == 0) ? 0 : redW[wid - 1];
                    int prefIncl = warpOff + incl;
                    int total = redW[31];
                    int S_t = total - (prefIncl - s);
                    int S_next = total - prefIncl;
                    if (S_t >= ktarget && S_next < ktarget) {
                        int Cc = S_next;
                        int bstar = tid * 4;
                        for (int b = tid * 4 + 3; b >= tid * 4; b--) {
                            Cc += (int)sHist[b];
                            if (Cc >= ktarget) { bstar = b; break; }
                        }
                        sChosen = bstar;
                    }
                    __syncthreads();
                    if (total < ktarget) thrH = 1u;
                    else thrH = Kb + ((unsigned)sChosen << hShift);
                    if (thrH >= prevThr) needExact = true;  // degenerate bin
                }
            } else {
                needExact = true;
            }
        }

        // ---- gather + (rare) exact-search retry on overflow ----
        int Gc = 0;
        for (int attempt = 0; attempt < 2; attempt++) {
            if (needExact) {
                unsigned pm = 0, pv = 0;
                int k = GTARGET;
                for (int sh = 30; sh >= 0; sh -= 3) {
                    unsigned long long c64 = 0;
                    for (int i = tid; i < SLOTS; i += 1024) {
                        unsigned h = sHi[i];
                        if (h >= 1u && h < prevThr && (h & pm) == pv)
                            c64 += 1ull << (((h >> sh) & 7u) * 8);
                    }
                    unsigned long long lo = spread4((unsigned)c64);
                    unsigned long long hi = spread4((unsigned)(c64 >> 32));
#pragma unroll
                    for (int o = 16; o; o >>= 1) {
                        lo += __shfl_down_sync(0xffffffffu, lo, o);
                        hi += __shfl_down_sync(0xffffffffu, hi, o);
                    }
                    if (lane == 0) { sWS[wid * 2] = lo; sWS[wid * 2 + 1] = hi; }
                    __syncthreads();
                    if (wid == 0) {
                        lo = sWS[lane * 2];
                        hi = sWS[lane * 2 + 1];
#pragma unroll
                        for (int o = 16; o; o >>= 1) {
                            lo += __shfl_down_sync(0xffffffffu, lo, o);
                            hi += __shfl_down_sync(0xffffffffu, hi, o);
                        }
                        if (lane == 0) {
                            unsigned cnt[8];
                            cnt[0] = (unsigned)(lo & 0xFFFF);
                            cnt[1] = (unsigned)((lo >> 16) & 0xFFFF);
                            cnt[2] = (unsigned)((lo >> 32) & 0xFFFF);
                            cnt[3] = (unsigned)((lo >> 48) & 0xFFFF);
                            cnt[4] = (unsigned)(hi & 0xFFFF);
                            cnt[5] = (unsigned)((hi >> 16) & 0xFFFF);
                            cnt[6] = (unsigned)((hi >> 32) & 0xFFFF);
                            cnt[7] = (unsigned)((hi >> 48) & 0xFFFF);
                            unsigned cum = 0;
                            int ch = 0;
                            unsigned ab = 0;
                            for (int b = 7; b >= 0; b--) {
                                if (cum + cnt[b] >= (unsigned)k) { ch = b; ab = cum; break; }
                                cum += cnt[b];
                            }
                            sChosen = ch;
                            sAbove = (int)ab;
                        }
                    }
                    __syncthreads();
                    pv |= ((unsigned)sChosen) << sh;
                    pm |= 7u << sh;
                    k -= sAbove;
                }
                thrH = pv;
            }
            // gather window [thrH, prevThr)
            if (tid == 0) gCnt2 = 0;
            sA[tid] = 0ull;
            gSlot[tid] = 0u;
            __syncthreads();
            for (int i = tid; i < SLOTS; i += 1024) {
                unsigned h = sHi[i];
                bool take = (h >= thrH) && (h < prevThr);
                unsigned m = __ballot_sync(0xffffffffu, take);
                if (m) {
                    int leader = __ffs(m) - 1;
                    unsigned base = 0;
                    if (lane == leader)
                        base = (unsigned)atomicAdd(&gCnt2, __popc(m));
                    base = __shfl_sync(0xffffffffu, base, leader);
                    if (take) {
                        unsigned pos = base + (unsigned)__popc(m & lt);
                        if (pos < GCAP) {
                            sA[pos] = ((unsigned long long)h << 32) | sLo[i];
                            gSlot[pos] = (unsigned)i;
                        }
                    }
                }
            }
            __syncthreads();
            Gc = gCnt2;
            if (Gc <= GCAP || needExact) break;
            needExact = true;  // histogram bin overflowed: redo exactly
        }
        if (Gc > GCAP) Gc = GCAP;  // needs 75+ identical float keys: impossible

        if (Gc > 0) {
            // ---- hybrid bitonic sort (descending): regs + shfl for j<32,
            //      smem exchange for j>=32. Element index = tid. ----
            unsigned long long r = sA[tid];
            unsigned s = gSlot[tid];
            for (int k2 = 2; k2 <= GCAP; k2 <<= 1) {
                for (int j = k2 >> 1; j > 0; j >>= 1) {
                    bool up = ((tid & k2) == 0);
                    bool lower = ((tid & j) == 0);
                    bool takeMax = (up == lower);
                    unsigned long long pr;
                    unsigned ps;
                    if (j >= 32) {
                        sA[tid] = r;
                        gSlot[tid] = s;
                        __syncthreads();
                        pr = sA[tid ^ j];
                        ps = gSlot[tid ^ j];
                        __syncthreads();
                    } else {
                        pr = __shfl_xor_sync(0xffffffffu, r, j);
                        ps = __shfl_xor_sync(0xffffffffu, s, j);
                    }
                    if ((pr > r) == takeMax) { r = pr; s = ps; }
                }
            }
            sA[tid] = r;
            gSlot[tid] = s;
            __syncthreads();

            // ---- fetch boxes ----
            {
                unsigned long long rv = r;
                float4 raw = make_float4(0.f, 0.f, 0.f, 0.f);
                float4 ofb = raw;
                float ar = 0.f;
                if (rv != 0ull) {
                    raw = gbx[s];
                    float off = (float)((~(unsigned)rv) % (unsigned)NCLS) * M;
                    ofb = make_float4(raw.x + off, raw.y + off, raw.z + off,
                                      raw.w + off);
                    ar = (ofb.z - ofb.x) * (ofb.w - ofb.y);
                }
                sRaw[tid] = raw;
                sOff[tid] = ofb;
                sAr[tid] = ar;
            }
            __syncthreads();

            // ---- lazy chunked greedy resolve (chunks of 64) ----
            for (int cbs = 0; cbs < Gc; cbs += 64) {
                int keptTot = sKeptTot;
                if (keptTot >= NDET) break;
                int ccnt = Gc - cbs;
                if (ccnt > 64) ccnt = 64;
                if (tid < 128) sRowC[tid] = 0u;
                else if (tid < 130) sPreC[tid - 128] = 0u;
                __syncthreads();
                {
                    int c = tid >> 4;
                    int sub = tid & 15;
                    if (c < ccnt) {
                        int j = cbs + c;
                        float4 q = sOff[j];
                        float aq = sAr[j];
                        bool dead = false;
                        for (int k2 = sub; k2 < keptTot; k2 += 16)
                            dead |= iou_sup(q, aq, kb[k2], kbA[k2]);
                        if (dead) atomicOr(&sPreC[c >> 5], 1u << (c & 31));
                        unsigned w0 = 0, w1 = 0;
                        for (int k2 = sub; k2 < ccnt; k2 += 16) {
                            if (k2 > c &&
                                iou_sup(q, aq, sOff[cbs + k2], sAr[cbs + k2])) {
                                if (k2 < 32) w0 |= 1u << k2;
                                else w1 |= 1u << (k2 - 32);
                            }
                        }
                        if (w0) atomicOr(&sRowC[c * 2], w0);
                        if (w1) atomicOr(&sRowC[c * 2 + 1], w1);
                    }
                }
                __syncthreads();
                if (tid == 0) {
                    unsigned d0 = sPreC[0], d1 = sPreC[1];
                    int kcnt = 0;
                    for (int c = 0; c < ccnt && keptTot + kcnt < NDET; c++) {
                        bool dead = (c < 32) ? ((d0 >> c) & 1u)
                                             : ((d1 >> (c - 32)) & 1u);
                        if (!dead) {
                            keptList[kcnt++] = (unsigned)(cbs + c);
                            d0 |= sRowC[c * 2];
                            d1 |= sRowC[c * 2 + 1];
                        }
                    }
                    sKcnt = kcnt;
                }
                __syncthreads();
                int kcnt = sKcnt;
                if (tid < kcnt) {
                    int j = (int)keptList[tid];
                    int row = keptTot + tid;
                    write_det(out, img, row, sA[j], sRaw[j], scale);
                    kb[row] = sOff[j];
                    kbA[row] = sAr[j];
                }
                __syncthreads();
                if (tid == 0) sKeptTot = keptTot + kcnt;
                __syncthreads();
            }
        }

        prevThr = thrH;
        __syncthreads();
        if (sKeptTot >= NDET || thrH == 1u) break;
    }

    // ---- zero-fill remaining rows + reset counter for next call ----
    int rows = sKeptTot;
    float* o2 = out + ((size_t)img * NDET + rows) * 6;
    for (int t = tid; t < (NDET - rows) * 6; t += 1024) o2[t] = 0.0f;
    if (tid == 0) g_cnt[img * 32] = 0;
}

// ---------------------------------------------------------------------------
extern "C" void kernel_launch(void* const* d_in, const int* in_sizes, int n_in,
                              void* d_out, int out_size) {
    static const int feats[5] = {64, 32, 16, 8, 4};
    const float* cls[5] = {0, 0, 0, 0, 0};
    const float* box[5] = {0, 0, 0, 0, 0};
    const float* anchors = 0;
    const float* scales = 0;
    const float* sizesp = 0;

    for (int j = 0; j < n_in; j++) {
        long sz = in_sizes[j];
        const float* p = (const float*)d_in[j];
        if (sz == 49104L * 4) anchors = p;
        else if (sz == 16) scales = p;
        else if (sz == 32) sizesp = p;
        else {
            for (int i = 0; i < 5; i++) {
                long ff = (long)feats[i] * feats[i];
                if (sz == 16L * 810 * ff) cls[i] = p;
                else if (sz == 16L * 36 * ff) box[i] = p;
            }
        }
    }

    dim3 gc(542, NIMG);
    k_collect<<<gc, 256>>>((const float4*)cls[0], (const float4*)cls[1],
                           (const float4*)cls[2], (const float4*)cls[3],
                           (const float4*)cls[4]);

    cudaFuncSetAttribute((const void*)k_sel,
                         cudaFuncAttributeMaxDynamicSharedMemorySize,
                         SKEY_CAP * 4);
    k_sel<<<NIMG, 1024, SKEY_CAP * 4>>>();

    dim3 gd(5, NIMG);
    k_decode<<<gd, 1024>>>(box[0], box[1], box[2], box[3], box[4], anchors,
                           scales, sizesp);

    cudaFuncSetAttribute((const void*)k_nms,
                         cudaFuncAttributeMaxDynamicSharedMemorySize,
                         NMS_SMEM);
    k_nms<<<NIMG, 1024, NMS_SMEM>>>(scales, (float*)d_out);
}